// round 1
// baseline (speedup 1.0000x reference)
#include <cuda_runtime.h>
#include <cstdint>

#define LSEQ 1024
#define DM   1024
#define BATCH 8
#define NH   16
#define DK   64
#define BHN  (BATCH*NH)     // 128
#define NREL 33
#define DI   4096
#define ROWS (BATCH*LSEQ)   // 8192

// ---------------- scratch (static device arrays; no allocation) ----------------
__device__ float g_Q[ROWS*DM];
__device__ float g_K[ROWS*DM];
__device__ float g_V[ROWS*DM];
__device__ float g_S[(size_t)BHN*LSEQ*LSEQ];      // 512 MB scores/probs
__device__ float g_Srel[(size_t)BHN*LSEQ*NREL];   // Qh . rel_k[r]
__device__ float g_Wb[(size_t)BHN*LSEQ*NREL];     // bucket-summed attention
__device__ float g_attn[ROWS*DM];
__device__ float g_tmp[ROWS*DM];
__device__ float g_ln1[ROWS*DM];
__device__ float g_h1[(size_t)ROWS*DI];
__device__ float g_t2[ROWS*DM];

// ---------------- reductions ----------------
__device__ __forceinline__ float block_sum(float v, float* red) {
    int lane = threadIdx.x & 31, w = threadIdx.x >> 5;
#pragma unroll
    for (int o = 16; o; o >>= 1) v += __shfl_xor_sync(0xffffffffu, v, o);
    if (lane == 0) red[w] = v;
    __syncthreads();
    if (w == 0) {
        float t = (lane < 8) ? red[lane] : 0.f;
#pragma unroll
        for (int o = 4; o; o >>= 1) t += __shfl_xor_sync(0xffffffffu, t, o);
        if (lane == 0) red[0] = t;
    }
    __syncthreads();
    float r = red[0];
    __syncthreads();
    return r;
}

__device__ __forceinline__ float block_max(float v, float* red) {
    int lane = threadIdx.x & 31, w = threadIdx.x >> 5;
#pragma unroll
    for (int o = 16; o; o >>= 1) v = fmaxf(v, __shfl_xor_sync(0xffffffffu, v, o));
    if (lane == 0) red[w] = v;
    __syncthreads();
    if (w == 0) {
        float t = (lane < 8) ? red[lane] : -3.4e38f;
#pragma unroll
        for (int o = 4; o; o >>= 1) t = fmaxf(t, __shfl_xor_sync(0xffffffffu, t, o));
        if (lane == 0) red[0] = t;
    }
    __syncthreads();
    float r = red[0];
    __syncthreads();
    return r;
}

// ---------------- generic GEMM: C[M,N] = A[M,K] @ W[K,N] + bias (opt relu) ----------------
// BM=128, BN=64, BK=16, 256 threads, 8x4 per thread
__global__ void gemm_bias(const float* __restrict__ A, const float* __restrict__ W,
                          const float* __restrict__ bias, float* __restrict__ C,
                          int M, int N, int K, int relu) {
    __shared__ __align__(16) float Ast[16][132];   // transposed: [k][m]
    __shared__ __align__(16) float Ws[16][68];     // [k][n]
    int tid = threadIdx.x;
    int tx = tid & 15, ty = tid >> 4;
    int bm = blockIdx.y * 128, bn = blockIdx.x * 64;
    float acc[8][4] = {};
    for (int k0 = 0; k0 < K; k0 += 16) {
#pragma unroll
        for (int i = 0; i < 2; i++) {
            int f = tid + i * 256;             // 0..511
            int r = f >> 2, c4 = f & 3;        // 128 rows x 4 float4
            float4 v = *(const float4*)(A + (size_t)(bm + r) * K + k0 + c4 * 4);
            Ast[c4 * 4 + 0][r] = v.x; Ast[c4 * 4 + 1][r] = v.y;
            Ast[c4 * 4 + 2][r] = v.z; Ast[c4 * 4 + 3][r] = v.w;
        }
        {
            int r = tid >> 4, c4 = tid & 15;   // 16 rows x 16 float4
            float4 v = *(const float4*)(W + (size_t)(k0 + r) * N + bn + c4 * 4);
            *(float4*)&Ws[r][c4 * 4] = v;
        }
        __syncthreads();
#pragma unroll
        for (int kk = 0; kk < 16; kk++) {
            float a[8], b[4];
#pragma unroll
            for (int i = 0; i < 8; i++) a[i] = Ast[kk][ty * 8 + i];
#pragma unroll
            for (int j = 0; j < 4; j++) b[j] = Ws[kk][tx * 4 + j];
#pragma unroll
            for (int i = 0; i < 8; i++)
#pragma unroll
                for (int j = 0; j < 4; j++) acc[i][j] += a[i] * b[j];
        }
        __syncthreads();
    }
#pragma unroll
    for (int i = 0; i < 8; i++) {
        int row = bm + ty * 8 + i;
#pragma unroll
        for (int j = 0; j < 4; j++) {
            int col = bn + tx * 4 + j;
            float v = acc[i][j] + bias[col];
            if (relu) v = fmaxf(v, 0.f);
            C[(size_t)row * N + col] = v;
        }
    }
}

// ---------------- S_rel[b,h,q,r] = Qh[b,q,h,:] . rel_k[r,:] ----------------
__global__ void srel_kernel(const float* __restrict__ rel_k) {
    int blk = blockIdx.x;               // b*L + q
    int b = blk >> 10, q = blk & 1023;
    __shared__ float qrow[DM];
    __shared__ float rk[NREL * DK];
    int tid = threadIdx.x;
    *(float4*)(qrow + tid * 4) = *(const float4*)(g_Q + (size_t)blk * DM + tid * 4);
    for (int o = tid; o < NREL * DK / 4; o += 256)
        *(float4*)(rk + o * 4) = *(const float4*)(rel_k + o * 4);
    __syncthreads();
    for (int o = tid; o < NH * NREL; o += 256) {
        int h = o / NREL, r = o % NREL;
        float acc = 0.f;
#pragma unroll
        for (int d = 0; d < DK; d++) acc += qrow[h * DK + d] * rk[r * DK + d];
        g_Srel[(((size_t)(b * NH + h)) * LSEQ + q) * NREL + r] = acc;
    }
}

// ---------------- scores: S = (Qh Kh^T + Srel-lookup) / 8 ----------------
__global__ void attn_scores() {
    int bh = blockIdx.z, b = bh >> 4, h = bh & 15;
    int bq = blockIdx.y * 64, bk = blockIdx.x * 64;
    __shared__ __align__(16) float Qs[64][68];   // [d][q]
    __shared__ __align__(16) float Ks[64][68];   // [d][k]
    int tid = threadIdx.x, tx = tid & 15, ty = tid >> 4;
    const float* Qb = g_Q + ((size_t)(b * LSEQ) + bq) * DM + h * DK;
    const float* Kb = g_K + ((size_t)(b * LSEQ) + bk) * DM + h * DK;
#pragma unroll
    for (int i = 0; i < 4; i++) {
        int f = tid + i * 256;              // 1024 float4
        int r = f >> 4, c4 = f & 15;
        float4 vq = *(const float4*)(Qb + (size_t)r * DM + c4 * 4);
        Qs[c4 * 4 + 0][r] = vq.x; Qs[c4 * 4 + 1][r] = vq.y;
        Qs[c4 * 4 + 2][r] = vq.z; Qs[c4 * 4 + 3][r] = vq.w;
        float4 vk = *(const float4*)(Kb + (size_t)r * DM + c4 * 4);
        Ks[c4 * 4 + 0][r] = vk.x; Ks[c4 * 4 + 1][r] = vk.y;
        Ks[c4 * 4 + 2][r] = vk.z; Ks[c4 * 4 + 3][r] = vk.w;
    }
    __syncthreads();
    float acc[4][4] = {};
#pragma unroll 16
    for (int kk = 0; kk < 64; kk++) {
        float a[4], bb[4];
#pragma unroll
        for (int i = 0; i < 4; i++) a[i] = Qs[kk][ty * 4 + i];
#pragma unroll
        for (int j = 0; j < 4; j++) bb[j] = Ks[kk][tx * 4 + j];
#pragma unroll
        for (int i = 0; i < 4; i++)
#pragma unroll
            for (int j = 0; j < 4; j++) acc[i][j] += a[i] * bb[j];
    }
    const float* srel = g_Srel + (size_t)bh * LSEQ * NREL;
#pragma unroll
    for (int i = 0; i < 4; i++) {
        int q = bq + ty * 4 + i;
#pragma unroll
        for (int j = 0; j < 4; j++) {
            int k = bk + tx * 4 + j;
            int d = k - q; d = max(-16, min(16, d));
            float val = (acc[i][j] + srel[(size_t)q * NREL + (d + 16)]) * 0.125f;
            g_S[((size_t)bh * LSEQ + q) * LSEQ + k] = val;
        }
    }
}

// ---------------- softmax rows (in place) + relative-position buckets ----------------
__global__ void softmax_bucket() {
    int row = blockIdx.x;               // bh*L + q
    int q = row & (LSEQ - 1);
    float* Sr = g_S + (size_t)row * LSEQ;
    int tid = threadIdx.x;
    __shared__ float sp[LSEQ];
    __shared__ float red[32];
    float4 v = *(float4*)(Sr + tid * 4);
    float m = fmaxf(fmaxf(v.x, v.y), fmaxf(v.z, v.w));
    m = block_max(m, red);
    float e0 = __expf(v.x - m), e1 = __expf(v.y - m);
    float e2 = __expf(v.z - m), e3 = __expf(v.w - m);
    float s = block_sum(e0 + e1 + e2 + e3, red);
    float inv = 1.f / s;
    float p0 = e0 * inv, p1 = e1 * inv, p2 = e2 * inv, p3 = e3 * inv;
    int k0 = tid * 4;
    sp[k0] = p0; sp[k0 + 1] = p1; sp[k0 + 2] = p2; sp[k0 + 3] = p3;
    *(float4*)(Sr + k0) = make_float4(p0, p1, p2, p3);
    float lo = 0.f, hi = 0.f;
    float pv[4] = {p0, p1, p2, p3};
#pragma unroll
    for (int u = 0; u < 4; u++) {
        int k = k0 + u;
        if (k <= q - 16) lo += pv[u];
        if (k >= q + 16) hi += pv[u];
    }
    lo = block_sum(lo, red);            // also serves as barrier for sp
    hi = block_sum(hi, red);
    float* Wr = g_Wb + (size_t)row * NREL;
    if (tid == 0) { Wr[0] = lo; Wr[32] = hi; }
    if (tid < 31) {
        int r = tid + 1;
        int k = q + r - 16;
        Wr[r] = (k >= 0 && k < LSEQ) ? sp[k] : 0.f;
    }
}

// ---------------- attn output: P @ Vh + Wb @ rel_v, written as [B,L,H*DV] ----------------
__global__ void attn_av(const float* __restrict__ rel_v) {
    int bh = blockIdx.z, b = bh >> 4, h = bh & 15;
    int bq = blockIdx.y * 64;
    __shared__ __align__(16) float Pt[64][68];   // [k][q]
    __shared__ __align__(16) float Vs[64][68];   // [k][d]
    int tid = threadIdx.x, tx = tid & 15, ty = tid >> 4;
    float acc[4][4] = {};
    for (int k0 = 0; k0 < LSEQ; k0 += 64) {
#pragma unroll
        for (int i = 0; i < 4; i++) {
            int f = tid + i * 256;
            int r = f >> 4, c4 = f & 15;
            float4 p = *(const float4*)(g_S + ((size_t)bh * LSEQ + bq + r) * LSEQ + k0 + c4 * 4);
            Pt[c4 * 4 + 0][r] = p.x; Pt[c4 * 4 + 1][r] = p.y;
            Pt[c4 * 4 + 2][r] = p.z; Pt[c4 * 4 + 3][r] = p.w;
            float4 vv = *(const float4*)(g_V + ((size_t)(b * LSEQ) + k0 + r) * DM + h * DK + c4 * 4);
            *(float4*)&Vs[r][c4 * 4] = vv;
        }
        __syncthreads();
#pragma unroll 16
        for (int kk = 0; kk < 64; kk++) {
            float a[4], bb[4];
#pragma unroll
            for (int i = 0; i < 4; i++) a[i] = Pt[kk][ty * 4 + i];
#pragma unroll
            for (int j = 0; j < 4; j++) bb[j] = Vs[kk][tx * 4 + j];
#pragma unroll
            for (int i = 0; i < 4; i++)
#pragma unroll
                for (int j = 0; j < 4; j++) acc[i][j] += a[i] * bb[j];
        }
        __syncthreads();
    }
    // rank-33 relative-V update; reuse smem
    float* Wl = &Pt[0][0];   // 64*33
    float* rv = &Vs[0][0];   // 33*64
    for (int o = tid; o < 64 * NREL; o += 256) {
        int m = o / NREL, r = o % NREL;
        Wl[o] = g_Wb[((size_t)bh * LSEQ + bq + m) * NREL + r];
    }
    for (int o = tid; o < NREL * DK; o += 256) rv[o] = rel_v[o];
    __syncthreads();
#pragma unroll 1
    for (int r = 0; r < NREL; r++) {
        float bb[4];
#pragma unroll
        for (int j = 0; j < 4; j++) bb[j] = rv[r * DK + tx * 4 + j];
#pragma unroll
        for (int i = 0; i < 4; i++) {
            float w = Wl[(ty * 4 + i) * NREL + r];
#pragma unroll
            for (int j = 0; j < 4; j++) acc[i][j] += w * bb[j];
        }
    }
#pragma unroll
    for (int i = 0; i < 4; i++) {
        int qi = bq + ty * 4 + i;
#pragma unroll
        for (int j = 0; j < 4; j++) {
            int d = tx * 4 + j;
            g_attn[((size_t)(b * LSEQ) + qi) * DM + h * DK + d] = acc[i][j];
        }
    }
}

// ---------------- layernorm: O = LN(X (+Res)) * g + b ----------------
__global__ void layernorm_k(const float* __restrict__ X, const float* __restrict__ Res,
                            const float* __restrict__ gam, const float* __restrict__ bet,
                            float* __restrict__ O) {
    int row = blockIdx.x, tid = threadIdx.x;
    __shared__ float red[32];
    float4 v = *(const float4*)(X + (size_t)row * DM + tid * 4);
    if (Res) {
        float4 rr = *(const float4*)(Res + (size_t)row * DM + tid * 4);
        v.x += rr.x; v.y += rr.y; v.z += rr.z; v.w += rr.w;
    }
    float s = block_sum(v.x + v.y + v.z + v.w, red);
    float s2 = block_sum(v.x * v.x + v.y * v.y + v.z * v.z + v.w * v.w, red);
    float mu = s * (1.f / DM);
    float var = s2 * (1.f / DM) - mu * mu;
    float rstd = rsqrtf(var + 1e-6f);
    float4 g4 = *(const float4*)(gam + tid * 4);
    float4 b4 = *(const float4*)(bet + tid * 4);
    float4 o;
    o.x = (v.x - mu) * rstd * g4.x + b4.x;
    o.y = (v.y - mu) * rstd * g4.y + b4.y;
    o.z = (v.z - mu) * rstd * g4.z + b4.z;
    o.w = (v.w - mu) * rstd * g4.w + b4.w;
    *(float4*)(O + (size_t)row * DM + tid * 4) = o;
}

// ---------------- launch ----------------
static void* sym_addr(const void* s) { void* p = nullptr; cudaGetSymbolAddress(&p, s); return p; }

extern "C" void kernel_launch(void* const* d_in, const int* in_sizes, int n_in,
                              void* d_out, int out_size) {
    const float* q    = (const float*)d_in[0];
    const float* k    = (const float*)d_in[1];
    const float* v    = (const float*)d_in[2];
    const float* wq   = (const float*)d_in[3];
    const float* bq   = (const float*)d_in[4];
    const float* wk   = (const float*)d_in[5];
    const float* bk   = (const float*)d_in[6];
    const float* wv   = (const float*)d_in[7];
    const float* bv   = (const float*)d_in[8];
    const float* wfc  = (const float*)d_in[9];
    const float* bfc  = (const float*)d_in[10];
    const float* w1   = (const float*)d_in[11];
    const float* b1   = (const float*)d_in[12];
    const float* w2   = (const float*)d_in[13];
    const float* b2   = (const float*)d_in[14];
    const float* ln_g = (const float*)d_in[15];
    const float* ln_b = (const float*)d_in[16];
    const float* relk = (const float*)d_in[17];
    const float* relv = (const float*)d_in[18];
    float* out = (float*)d_out;

    float* pQ    = (float*)sym_addr(g_Q);
    float* pK    = (float*)sym_addr(g_K);
    float* pV    = (float*)sym_addr(g_V);
    float* pAttn = (float*)sym_addr(g_attn);
    float* pTmp  = (float*)sym_addr(g_tmp);
    float* pLn1  = (float*)sym_addr(g_ln1);
    float* pH1   = (float*)sym_addr(g_h1);
    float* pT2   = (float*)sym_addr(g_t2);

    dim3 gD(DM / 64, ROWS / 128);     // N=1024 GEMMs
    dim3 gI(DI / 64, ROWS / 128);     // N=4096 GEMM

    gemm_bias<<<gD, 256>>>(q, wq, bq, pQ, ROWS, DM, DM, 0);
    gemm_bias<<<gD, 256>>>(k, wk, bk, pK, ROWS, DM, DM, 0);
    gemm_bias<<<gD, 256>>>(v, wv, bv, pV, ROWS, DM, DM, 0);

    srel_kernel<<<ROWS, 256>>>(relk);

    dim3 gs(LSEQ / 64, LSEQ / 64, BHN);
    attn_scores<<<gs, 256>>>();

    softmax_bucket<<<BHN * LSEQ, 256>>>();

    dim3 gav(1, LSEQ / 64, BHN);
    attn_av<<<gav, 256>>>(relv);

    gemm_bias<<<gD, 256>>>(pAttn, wfc, bfc, pTmp, ROWS, DM, DM, 0);
    layernorm_k<<<ROWS, 256>>>(pTmp, q, ln_g, ln_b, pLn1);

    gemm_bias<<<gI, 256>>>(pLn1, w1, b1, pH1, ROWS, DI, DM, 1);
    gemm_bias<<<gD, 256>>>(pH1, w2, b2, pT2, ROWS, DM, DI, 0);
    layernorm_k<<<ROWS, 256>>>(pT2, pLn1, ln_g, ln_b, out);
}